// round 2
// baseline (speedup 1.0000x reference)
#include <cuda_runtime.h>
#include <cstdint>

// Problem constants (fixed shapes per reference)
#define NTOK 8192
#define INF  1024
#define OUTF 1024
#define GS   8
#define KDIM (INF * 9)          // 9216 = silu + 8 laplacian features per input dim

// Scratch (device globals: allocation-free rule)
static __device__ float g_phi[(size_t)NTOK * KDIM];   // 302 MB feature matrix, tf32-rounded
static __device__ float g_w[(size_t)OUTF * KDIM];     // 37.7 MB combined weights, tf32-rounded

__device__ __forceinline__ float tf32r(float x) {
    uint32_t y;
    asm("cvt.rna.tf32.f32 %0, %1;" : "=r"(y) : "f"(x));
    return __uint_as_float(y);
}

// ---------------------------------------------------------------------------
// Kernel 1: combined weight matrix  W[o][c*INF + i]
//   c=0   -> base_weight[o,i]
//   c=1+g -> spline_weight[o,i,g] * spline_scaler[o,i]
// ---------------------------------------------------------------------------
__global__ void prep_w_kernel(const float* __restrict__ bw,
                              const float* __restrict__ sw,
                              const float* __restrict__ sc) {
    int idx = blockIdx.x * blockDim.x + threadIdx.x;     // o*INF + i
    if (idx >= OUTF * INF) return;
    int o = idx / INF;
    int i = idx - o * INF;
    size_t base = (size_t)o * KDIM + i;
    float scaler = sc[idx];
    g_w[base] = tf32r(bw[idx]);
    #pragma unroll
    for (int g = 0; g < GS; g++) {
        g_w[base + (size_t)(1 + g) * INF] = tf32r(sw[(size_t)idx * GS + g] * scaler);
    }
}

// ---------------------------------------------------------------------------
// Kernel 2: feature matrix  Phi[n][c*INF + i]
//   c=0   -> silu(x)
//   c=1+g -> exp(-|x - grid[i,g]|)   (sigma = 1)
// ---------------------------------------------------------------------------
__global__ void prep_phi_kernel(const float* __restrict__ x,
                                const float* __restrict__ grid) {
    int idx = blockIdx.x * blockDim.x + threadIdx.x;     // n*INF + i
    if (idx >= NTOK * INF) return;
    int n = idx / INF;
    int i = idx - n * INF;
    float xv = x[idx];
    size_t base = (size_t)n * KDIM + i;
    // silu(x) = x / (1 + exp(-x))
    float s = xv / (1.0f + __expf(-xv));
    g_phi[base] = tf32r(s);
    #pragma unroll
    for (int g = 0; g < GS; g++) {
        float gv = grid[i * GS + g];
        float kv = __expf(-fabsf(xv - gv));
        g_phi[base + (size_t)(1 + g) * INF] = tf32r(kv);
    }
}

// ---------------------------------------------------------------------------
// Kernel 3: GEMM  out[8192,1024] = Phi[8192,9216] @ W[1024,9216]^T
//   tf32 mma.sync m16n8k8, fp32 accumulate.
//   CTA tile 128x128x32, 256 threads, warps 4(m) x 2(n), warp tile 32x64.
//   cp.async double-buffered SMEM, pad stride 36 (conflict-free frag loads).
// ---------------------------------------------------------------------------
#define BM 128
#define BN 128
#define BK 32
#define LDA 36
#define STAGE_A (BM * LDA)                     // 4608 floats
#define STAGE_B (BN * LDA)
#define SMEM_FLOATS (2 * (STAGE_A + STAGE_B))  // 18432 floats = 73728 B

__device__ __forceinline__ void cp_async16(float* smem_ptr, const float* gptr) {
    uint32_t s = (uint32_t)__cvta_generic_to_shared(smem_ptr);
    asm volatile("cp.async.cg.shared.global [%0], [%1], 16;\n" :: "r"(s), "l"(gptr));
}

__device__ __forceinline__ void mma_tf32(float c[4], const uint32_t a[4], const uint32_t b[2]) {
    asm volatile(
        "mma.sync.aligned.m16n8k8.row.col.f32.tf32.tf32.f32 "
        "{%0,%1,%2,%3}, {%4,%5,%6,%7}, {%8,%9}, {%0,%1,%2,%3};\n"
        : "+f"(c[0]), "+f"(c[1]), "+f"(c[2]), "+f"(c[3])
        : "r"(a[0]), "r"(a[1]), "r"(a[2]), "r"(a[3]), "r"(b[0]), "r"(b[1]));
}

__global__ void __launch_bounds__(256) gemm_tf32_kernel(float* __restrict__ C) {
    extern __shared__ float sm[];
    float* As = sm;                   // [2][BM][LDA]
    float* Bs = sm + 2 * STAGE_A;     // [2][BN][LDA]

    const float* __restrict__ A = g_phi;
    const float* __restrict__ B = g_w;

    const int m0 = blockIdx.y * BM;
    const int n0 = blockIdx.x * BN;
    const int tid = threadIdx.x;
    const int warp = tid >> 5;
    const int lane = tid & 31;
    const int gid = lane >> 2;        // 0..7
    const int tig = lane & 3;         // 0..3
    const int wm = (warp & 3) * 32;   // warp m-offset
    const int wn = (warp >> 2) * 64;  // warp n-offset

    // Global->SMEM mapping: 2 threads per row, each copies 4x float4 (64B)
    const int lrow = tid >> 1;            // 0..127
    const int lc0  = (tid & 1) * 16;      // 0 or 16

    const float* Ag = A + (size_t)(m0 + lrow) * KDIM + lc0;
    const float* Bg = B + (size_t)(n0 + lrow) * KDIM + lc0;
    float* Asw = As + lrow * LDA + lc0;
    float* Bsw = Bs + lrow * LDA + lc0;

    float acc[2][8][4];
    #pragma unroll
    for (int mi = 0; mi < 2; mi++)
        #pragma unroll
        for (int ni = 0; ni < 8; ni++)
            #pragma unroll
            for (int r = 0; r < 4; r++)
                acc[mi][ni][r] = 0.0f;

    const int KT = KDIM / BK;   // 288

    // Prologue: stage 0
    #pragma unroll
    for (int j = 0; j < 4; j++) {
        cp_async16(Asw + j * 4, Ag + j * 4);
        cp_async16(Bsw + j * 4, Bg + j * 4);
    }
    asm volatile("cp.async.commit_group;\n");
    asm volatile("cp.async.wait_group 0;\n");
    __syncthreads();

    for (int kt = 0; kt < KT; kt++) {
        const int s = kt & 1;
        if (kt + 1 < KT) {
            const float* ag = Ag + (kt + 1) * BK;
            const float* bg = Bg + (kt + 1) * BK;
            float* as = Asw + (s ^ 1) * STAGE_A;
            float* bs = Bsw + (s ^ 1) * STAGE_B;
            #pragma unroll
            for (int j = 0; j < 4; j++) {
                cp_async16(as + j * 4, ag + j * 4);
                cp_async16(bs + j * 4, bg + j * 4);
            }
            asm volatile("cp.async.commit_group;\n");
        }

        const float* asb = As + s * STAGE_A;
        const float* bsb = Bs + s * STAGE_B;

        #pragma unroll
        for (int ks = 0; ks < 4; ks++) {
            const int kb = ks * 8;
            uint32_t a[2][4], b[8][2];
            #pragma unroll
            for (int mi = 0; mi < 2; mi++) {
                const float* ap = asb + (wm + mi * 16 + gid) * LDA + kb + tig;
                a[mi][0] = __float_as_uint(ap[0]);
                a[mi][1] = __float_as_uint(ap[8 * LDA]);
                a[mi][2] = __float_as_uint(ap[4]);
                a[mi][3] = __float_as_uint(ap[8 * LDA + 4]);
            }
            #pragma unroll
            for (int ni = 0; ni < 8; ni++) {
                const float* bp = bsb + (wn + ni * 8 + gid) * LDA + kb + tig;
                b[ni][0] = __float_as_uint(bp[0]);
                b[ni][1] = __float_as_uint(bp[4]);
            }
            #pragma unroll
            for (int mi = 0; mi < 2; mi++)
                #pragma unroll
                for (int ni = 0; ni < 8; ni++)
                    mma_tf32(acc[mi][ni], a[mi], b[ni]);
        }

        if (kt + 1 < KT) asm volatile("cp.async.wait_group 0;\n");
        __syncthreads();
    }

    // Epilogue: fp32 accumulators -> C, float2 stores (8B aligned: col even)
    #pragma unroll
    for (int mi = 0; mi < 2; mi++) {
        const int row = m0 + wm + mi * 16 + gid;
        #pragma unroll
        for (int ni = 0; ni < 8; ni++) {
            const int col = n0 + wn + ni * 8 + tig * 2;
            *reinterpret_cast<float2*>(C + (size_t)row * OUTF + col) =
                make_float2(acc[mi][ni][0], acc[mi][ni][1]);
            *reinterpret_cast<float2*>(C + (size_t)(row + 8) * OUTF + col) =
                make_float2(acc[mi][ni][2], acc[mi][ni][3]);
        }
    }
}

// ---------------------------------------------------------------------------
extern "C" void kernel_launch(void* const* d_in, const int* in_sizes, int n_in,
                              void* d_out, int out_size) {
    const float* x    = (const float*)d_in[0];   // (8192, 1024)
    const float* bw   = (const float*)d_in[1];   // (1024, 1024)
    const float* sw   = (const float*)d_in[2];   // (1024, 1024, 8)
    const float* sc   = (const float*)d_in[3];   // (1024, 1024)
    const float* grid = (const float*)d_in[4];   // (1024, 8)
    float* out = (float*)d_out;                  // (8192, 1024)

    (void)in_sizes; (void)n_in; (void)out_size;

    // 72KB dynamic SMEM for the GEMM (idempotent; not a stream op, capture-safe)
    cudaFuncSetAttribute(gemm_tf32_kernel,
                         cudaFuncAttributeMaxDynamicSharedMemorySize,
                         SMEM_FLOATS * (int)sizeof(float));

    prep_w_kernel<<<(OUTF * INF + 255) / 256, 256>>>(bw, sw, sc);
    prep_phi_kernel<<<(NTOK * INF + 255) / 256, 256>>>(x, grid);

    dim3 grid_dim(OUTF / BN, NTOK / BM);   // (8, 64)
    gemm_tf32_kernel<<<grid_dim, 256, SMEM_FLOATS * sizeof(float)>>>(out);
}

// round 4
// speedup vs baseline: 2.2387x; 2.2387x over previous
#include <cuda_runtime.h>
#include <cuda_fp16.h>
#include <cstdint>

// ---------------------------------------------------------------------------
// Problem constants
// ---------------------------------------------------------------------------
#define NTOK 8192
#define INF  1024
#define OUTF 1024
#define GS   8
#define KDIM (INF * 9)          // 9216 = silu + 8 laplacian features

// Scratch (device globals: allocation-free rule). fp16 halves the footprint.
static __device__ __align__(256) __half g_phi[(size_t)NTOK * KDIM];   // 151 MB
static __device__ __align__(256) __half g_w[(size_t)OUTF * KDIM];     // 18.9 MB

// ---------------------------------------------------------------------------
// Prep kernels: fold weights / build features, store fp16
// ---------------------------------------------------------------------------
__global__ void prep_w_kernel(const float* __restrict__ bw,
                              const float* __restrict__ sw,
                              const float* __restrict__ sc) {
    int idx = blockIdx.x * blockDim.x + threadIdx.x;     // o*INF + i
    if (idx >= OUTF * INF) return;
    int o = idx / INF;
    int i = idx - o * INF;
    size_t base = (size_t)o * KDIM + i;
    float scaler = sc[idx];
    g_w[base] = __float2half(bw[idx]);
    #pragma unroll
    for (int g = 0; g < GS; g++)
        g_w[base + (size_t)(1 + g) * INF] = __float2half(sw[(size_t)idx * GS + g] * scaler);
}

__global__ void prep_phi_kernel(const float* __restrict__ x,
                                const float* __restrict__ grid) {
    int idx = blockIdx.x * blockDim.x + threadIdx.x;     // n*INF + i
    if (idx >= NTOK * INF) return;
    int n = idx / INF;
    int i = idx - n * INF;
    float xv = x[idx];
    size_t base = (size_t)n * KDIM + i;
    g_phi[base] = __float2half(xv / (1.0f + __expf(-xv)));   // silu
    #pragma unroll
    for (int g = 0; g < GS; g++) {
        float gv = grid[i * GS + g];
        g_phi[base + (size_t)(1 + g) * INF] = __float2half(__expf(-fabsf(xv - gv)));
    }
}

// ---------------------------------------------------------------------------
// fp16 GEMM:  C[8192,1024] = Phi[8192,9216] @ W[1024,9216]^T  (fp32 accum)
//   mma.sync m16n8k16.row.col, CTA tile 128x128x64(halves), 256 thr,
//   warps 4(m) x 2(n) -> warp tile 32x64. 3-stage cp.async, 2 CTAs/SM.
//   SMEM row = 64 halves = 128B = 8 x 16B chunks, XOR swizzle chunk^(row&7).
// ---------------------------------------------------------------------------
#define BM 128
#define BN 128
#define BKH 64                        // halves per K-tile (128 bytes)
#define STAGES 3
#define A_BYTES (BM * 128)            // 16 KB
#define B_BYTES (BN * 128)            // 16 KB
#define STAGE_BYTES (A_BYTES + B_BYTES)          // 32 KB
#define SMEM_BYTES (STAGES * STAGE_BYTES)        // 96 KB
#define KT (KDIM / BKH)               // 144

__device__ __forceinline__ void cp_async16(uint32_t smem_addr, const void* gptr) {
    asm volatile("cp.async.cg.shared.global [%0], [%1], 16;\n" :: "r"(smem_addr), "l"(gptr));
}
__device__ __forceinline__ uint32_t smem_u32(const void* p) {
    uint32_t a;
    asm("{ .reg .u64 t; cvta.to.shared.u64 t, %1; cvt.u32.u64 %0, t; }" : "=r"(a) : "l"(p));
    return a;
}
__device__ __forceinline__ uint32_t lds32(uint32_t addr) {
    uint32_t v;
    asm volatile("ld.shared.b32 %0, [%1];" : "=r"(v) : "r"(addr));
    return v;
}
__device__ __forceinline__ void mma_f16(float c[4], const uint32_t a[4], const uint32_t b[2]) {
    asm volatile(
        "mma.sync.aligned.m16n8k16.row.col.f32.f16.f16.f32 "
        "{%0,%1,%2,%3}, {%4,%5,%6,%7}, {%8,%9}, {%0,%1,%2,%3};\n"
        : "+f"(c[0]), "+f"(c[1]), "+f"(c[2]), "+f"(c[3])
        : "r"(a[0]), "r"(a[1]), "r"(a[2]), "r"(a[3]), "r"(b[0]), "r"(b[1]));
}

// swizzled byte offset within a stage region for (row, 16B-chunk)
__device__ __forceinline__ uint32_t swz(int row, int chunk) {
    return (uint32_t)(row * 128 + ((chunk ^ (row & 7)) << 4));
}

__global__ void __launch_bounds__(256, 2) gemm_f16_kernel(float* __restrict__ C) {
    extern __shared__ __align__(1024) char smem[];
    const uint32_t sb = smem_u32(smem);

    const int tid  = threadIdx.x;
    const int warp = tid >> 5;
    const int lane = tid & 31;
    const int g    = lane >> 2;       // 0..7
    const int t4   = lane & 3;        // 0..3
    const int wm   = (warp & 3) * 32;
    const int wn   = (warp >> 2) * 64;

    const int m0 = blockIdx.y * BM;
    const int n0 = blockIdx.x * BN;

    // ---- cp.async addressing: thread t -> row t>>1, chunks (t&1)*4 + 0..3 ----
    const int crow = tid >> 1;
    const int cch0 = (tid & 1) * 4;
    const __half* Ag = g_phi + (size_t)(m0 + crow) * KDIM + cch0 * 8;
    const __half* Bg = g_w   + (size_t)(n0 + crow) * KDIM + cch0 * 8;
    uint32_t Asw[4], Bsw[4];
    #pragma unroll
    for (int j = 0; j < 4; j++) {
        Asw[j] = sb + swz(crow, cch0 + j);
        Bsw[j] = sb + A_BYTES + swz(crow, cch0 + j);
    }

    float acc[2][8][4];
    #pragma unroll
    for (int mi = 0; mi < 2; mi++)
        #pragma unroll
        for (int ni = 0; ni < 8; ni++)
            #pragma unroll
            for (int r = 0; r < 4; r++) acc[mi][ni][r] = 0.0f;

    // ---- prologue: stages 0,1 ----
    #pragma unroll
    for (int s = 0; s < 2; s++) {
        const uint32_t so = s * STAGE_BYTES;
        const int ko = s * BKH;
        #pragma unroll
        for (int j = 0; j < 4; j++) {
            cp_async16(Asw[j] + so, Ag + ko + j * 8);
            cp_async16(Bsw[j] + so, Bg + ko + j * 8);
        }
        asm volatile("cp.async.commit_group;\n");
    }

    // fragment base offsets (lane-dependent pieces precomputed)
    const uint32_t aoff = t4 * 4;     // byte offset inside 16B chunk

    for (int kt = 0; kt < KT; kt++) {
        if (kt < KT - 1) asm volatile("cp.async.wait_group 1;\n");
        else             asm volatile("cp.async.wait_group 0;\n");
        __syncthreads();

        if (kt + 2 < KT) {
            const uint32_t so = ((kt + 2) % STAGES) * STAGE_BYTES;
            const int ko = (kt + 2) * BKH;
            #pragma unroll
            for (int j = 0; j < 4; j++) {
                cp_async16(Asw[j] + so, Ag + ko + j * 8);
                cp_async16(Bsw[j] + so, Bg + ko + j * 8);
            }
            asm volatile("cp.async.commit_group;\n");
        }

        const uint32_t as = sb + (kt % STAGES) * STAGE_BYTES;
        const uint32_t bs = as + A_BYTES;

        #pragma unroll
        for (int ks = 0; ks < 4; ks++) {          // four k16 steps
            const int ch = 2 * ks;
            uint32_t a[2][4], b[8][2];
            #pragma unroll
            for (int mi = 0; mi < 2; mi++) {
                const int r = wm + mi * 16 + g;
                a[mi][0] = lds32(as + swz(r,     ch)     + aoff);
                a[mi][1] = lds32(as + swz(r + 8, ch)     + aoff);
                a[mi][2] = lds32(as + swz(r,     ch + 1) + aoff);
                a[mi][3] = lds32(as + swz(r + 8, ch + 1) + aoff);
            }
            #pragma unroll
            for (int ni = 0; ni < 8; ni++) {
                const int rn = wn + ni * 8 + g;
                b[ni][0] = lds32(bs + swz(rn, ch)     + aoff);
                b[ni][1] = lds32(bs + swz(rn, ch + 1) + aoff);
            }
            #pragma unroll
            for (int mi = 0; mi < 2; mi++)
                #pragma unroll
                for (int ni = 0; ni < 8; ni++)
                    mma_f16(acc[mi][ni], a[mi], b[ni]);
        }
    }

    // ---- epilogue: float2 stores (same mapping as validated R2) ----
    #pragma unroll
    for (int mi = 0; mi < 2; mi++) {
        const int row = m0 + wm + mi * 16 + g;
        #pragma unroll
        for (int ni = 0; ni < 8; ni++) {
            const int col = n0 + wn + ni * 8 + t4 * 2;
            *reinterpret_cast<float2*>(C + (size_t)row * OUTF + col) =
                make_float2(acc[mi][ni][0], acc[mi][ni][1]);
            *reinterpret_cast<float2*>(C + (size_t)(row + 8) * OUTF + col) =
                make_float2(acc[mi][ni][2], acc[mi][ni][3]);
        }
    }
}

// ---------------------------------------------------------------------------
extern "C" void kernel_launch(void* const* d_in, const int* in_sizes, int n_in,
                              void* d_out, int out_size) {
    const float* x    = (const float*)d_in[0];   // (8192, 1024)
    const float* bw   = (const float*)d_in[1];   // (1024, 1024)
    const float* sw   = (const float*)d_in[2];   // (1024, 1024, 8)
    const float* sc   = (const float*)d_in[3];   // (1024, 1024)
    const float* grid = (const float*)d_in[4];   // (1024, 8)
    float* out = (float*)d_out;                  // (8192, 1024)

    (void)in_sizes; (void)n_in; (void)out_size;

    cudaFuncSetAttribute(gemm_f16_kernel,
                         cudaFuncAttributeMaxDynamicSharedMemorySize, SMEM_BYTES);

    prep_w_kernel<<<(OUTF * INF + 255) / 256, 256>>>(bw, sw, sc);
    prep_phi_kernel<<<(NTOK * INF + 255) / 256, 256>>>(x, grid);

    dim3 gdim(OUTF / BN, NTOK / BM);   // (8, 64) = 512 CTAs
    gemm_f16_kernel<<<gdim, 256, SMEM_BYTES>>>(out);
}